// round 14
// baseline (speedup 1.0000x reference)
#include <cuda_runtime.h>
#include <cuda_fp16.h>
#include <cstdint>
#include <cstddef>

#define DINLINE __device__ __forceinline__

namespace {
constexpr int E       = 1024;
constexpr int KC      = 2048;
constexpr int MAXROWS = 32000;

constexpr int BM = 128;          // CTA rows
constexpr int BN = 128;          // CTA centroids
constexpr int BK = 128;          // k-chunk: 128 int8 = 128B row (SW128)
constexpr int NK = E / BK;       // 8
constexpr int NSTAGE = 3;
constexpr int GTHREADS = 256;    // 8 warps: 4(m) x 2(n), warp tile 32x64

constexpr int STAGE_BYTES = (BM + BN) * BK;         // 32KB
constexpr int OFF_B       = BM * BK;                // B tile after A in stage
constexpr int OFF_CNORM   = NSTAGE * STAGE_BYTES;   // 96KB
constexpr int GSMEM_TOTAL = OFF_CNORM + BN * 4;     // 98816 -> 2 CTAs/SM

constexpr float QS     = 21.0f;              // int8 quant scale
constexpr float SCALE2 = 2.0f / (QS * QS);   // dist = cnorm - SCALE2*dot_int
constexpr float DOFF   = 1024.0f;            // center dists before fp16 store
constexpr float MARGIN = 12.0f;              // ~8-sigma of int8-quant dist err
constexpr int   CAP    = 128;                // candidate cap per row
constexpr int   NCHK   = 32;                 // 64-col min-chunks per row

constexpr int XBLK = 2048;                   // x elems per prologue block
}

// ---------------- device scratch --------------------------------------------
__device__ int8_t g_x_i8[MAXROWS * E];   // 32MB
__device__ int8_t g_c_i8[KC * E];        // 2MB
__device__ __align__(16) __half g_D[(size_t)MAXROWS * KC]; // 131MB dists - DOFF
__device__ float  g_pmin[(size_t)MAXROWS * NCHK];          // 4MB per-chunk mins
__device__ float  g_cnorm[KC];

// ---------------- helpers ----------------------------------------------------
DINLINE uint32_t smem_u32(const void* p) {
    uint32_t a;
    asm("{ .reg .u64 t; cvta.to.shared.u64 t, %1; cvt.u32.u64 %0, t; }"
        : "=r"(a) : "l"(p));
    return a;
}
DINLINE uint32_t sw128(uint32_t o) { return o ^ ((o >> 3) & 0x70); }
DINLINE uint32_t swz(uint32_t rel) {           // 1024-aligned region swizzle
    return (rel & ~1023u) | sw128(rel & 1023u);
}

DINLINE void cp16(uint32_t dst, const void* src) {
    asm volatile("cp.async.cg.shared.global [%0], [%1], 16;"
                 :: "r"(dst), "l"(src) : "memory");
}
#define CP_COMMIT()      asm volatile("cp.async.commit_group;" ::: "memory")
#define CP_WAIT_GROUP(n) asm volatile("cp.async.wait_group %0;" :: "n"(n) : "memory")

DINLINE void ldm_x4(uint32_t& r0, uint32_t& r1, uint32_t& r2, uint32_t& r3,
                    uint32_t addr) {
    asm volatile("ldmatrix.sync.aligned.m8n8.x4.shared.b16 {%0,%1,%2,%3}, [%4];"
                 : "=r"(r0), "=r"(r1), "=r"(r2), "=r"(r3) : "r"(addr));
}
// int8 MMA: D(s32) = A(s8)*B(s8) + C(s32), 16x8x32
DINLINE void mma_s8(int& d0, int& d1, int& d2, int& d3,
                    uint32_t a0, uint32_t a1, uint32_t a2, uint32_t a3,
                    uint32_t b0, uint32_t b1) {
    asm volatile("mma.sync.aligned.m16n8k32.row.col.s32.s8.s8.s32 "
                 "{%0,%1,%2,%3}, {%4,%5,%6,%7}, {%8,%9}, {%0,%1,%2,%3};"
                 : "+r"(d0), "+r"(d1), "+r"(d2), "+r"(d3)
                 : "r"(a0), "r"(a1), "r"(a2), "r"(a3), "r"(b0), "r"(b1));
}

DINLINE int q8(float v) {
    int i = __float2int_rn(v * QS);
    return max(-127, min(127, i));
}

// ---------------- merged prologue: quantize x + quantize c + cnorm -----------
__global__ void prologue_kernel(const float* __restrict__ x,
                                const float* __restrict__ cen, int nxb) {
    const int tid = threadIdx.x;
    if (blockIdx.x < nxb) {
        const size_t base = (size_t)blockIdx.x * XBLK + (size_t)tid * 8;
        const float4* s4 = reinterpret_cast<const float4*>(x + base);
        float4 a = s4[0], b = s4[1];
        float v[8] = {a.x, a.y, a.z, a.w, b.x, b.y, b.z, b.w};
        uint2 o;
        int8_t* p = reinterpret_cast<int8_t*>(&o);
        #pragma unroll
        for (int j = 0; j < 8; j++) p[j] = (int8_t)q8(v[j]);
        *reinterpret_cast<uint2*>(g_x_i8 + base) = o;
    } else {
        const int row = blockIdx.x - nxb;
        const float4 a = reinterpret_cast<const float4*>(cen + (size_t)row * E)[tid];
        float v[4] = {a.x, a.y, a.z, a.w};
        uint32_t o;
        int8_t* p = reinterpret_cast<int8_t*>(&o);
        float s = 0.f;
        #pragma unroll
        for (int j = 0; j < 4; j++) {
            p[j] = (int8_t)q8(v[j]);
            s = fmaf(v[j], v[j], s);
        }
        *reinterpret_cast<uint32_t*>(g_c_i8 + (size_t)row * E + tid * 4) = o;

        __shared__ float sm[8];
        #pragma unroll
        for (int off = 16; off > 0; off >>= 1)
            s += __shfl_down_sync(0xffffffffu, s, off);
        if ((tid & 31) == 0) sm[tid >> 5] = s;
        __syncthreads();
        if (tid < 8) {
            s = sm[tid];
            #pragma unroll
            for (int off = 4; off > 0; off >>= 1)
                s += __shfl_down_sync(0xffu, s, off);
            if (tid == 0) g_cnorm[row] = s;
        }
    }
}

// ---------------- GEMM (s8 in, s32 acc): D = cnorm - SCALE2*dot - DOFF -------
DINLINE void fill_stage(int kt, int row0, int n0, int tid, uint32_t sbase) {
    const uint32_t soff = (uint32_t)(kt % NSTAGE) * STAGE_BYTES;
    const int r    = tid >> 1;          // 0..127 row within tile
    const int half = tid & 1;           // bytes 0-63 / 64-127 of the row
    const int k0   = kt * BK + half * 64;
    const int8_t* xs = g_x_i8 + (size_t)(row0 + r) * E + k0;
    const int8_t* cs = g_c_i8 + (size_t)(n0 + r) * E + k0;
    const uint32_t base = (uint32_t)r * 128u + (uint32_t)half * 64u;
    #pragma unroll
    for (int q = 0; q < 4; q++)
        cp16(sbase + soff + sw128(base + q * 16), xs + q * 16);
    #pragma unroll
    for (int q = 0; q < 4; q++)
        cp16(sbase + soff + OFF_B + sw128(base + q * 16), cs + q * 16);
}

__global__ void __launch_bounds__(GTHREADS, 2)
gemm_s8_kernel() {
    extern __shared__ __align__(1024) char smem[];
    const uint32_t sbase = smem_u32(smem);
    const int tid  = threadIdx.x;
    const int lane = tid & 31;
    const int wid  = tid >> 5;
    const int wm   = wid & 3;           // warp m: 0..3 (32 rows each)
    const int wn   = wid >> 2;          // warp n: 0..1 (64 cols each)
    const int n0   = blockIdx.x * BN;
    const int row0 = blockIdx.y * BM;

    float* s_cnorm = reinterpret_cast<float*>(smem + OFF_CNORM);
    if (tid < BN) s_cnorm[tid] = g_cnorm[n0 + tid];

    int acc[2][8][4];                   // s32 accumulators
    #pragma unroll
    for (int mt = 0; mt < 2; mt++)
        #pragma unroll
        for (int nt = 0; nt < 8; nt++)
            #pragma unroll
            for (int v = 0; v < 4; v++) acc[mt][nt][v] = 0;

    fill_stage(0, row0, n0, tid, sbase); CP_COMMIT();
    fill_stage(1, row0, n0, tid, sbase); CP_COMMIT();

    // ldmatrix lane-address components (byte windows; identical to fp16 code)
    const int lrow16 = lane & 15;       // row within 16
    const int lksel  = lane >> 4;       // 0: bytes 0-15, 1: bytes 16-31
    const int bgrp   = lane >> 3;       // B x4 group 0..3
    const int brow   = lane & 7;

    for (int kt = 0; kt < NK; kt++) {
        CP_WAIT_GROUP(1);               // stage kt resident
        __syncthreads();                // reads of slot kt-1 done

        const uint32_t sa = sbase + (uint32_t)(kt % NSTAGE) * STAGE_BYTES;
        const uint32_t sb = sa + OFF_B;

        // preload slice-0 fragments before issuing next fill
        uint32_t bF[2][8][2];
        #pragma unroll
        for (int np = 0; np < 4; np++) {
            uint32_t n = (uint32_t)(wn * 64 + (np * 2 + (bgrp >> 1)) * 8 + brow);
            uint32_t addr = sb + swz(n * 128u + (uint32_t)(bgrp & 1) * 16u);
            uint32_t r0, r1, r2, r3;
            ldm_x4(r0, r1, r2, r3, addr);
            bF[0][np * 2][0] = r0; bF[0][np * 2][1] = r1;
            bF[0][np * 2 + 1][0] = r2; bF[0][np * 2 + 1][1] = r3;
        }
        uint32_t aF0[2][4];
        #pragma unroll
        for (int mt = 0; mt < 2; mt++) {
            uint32_t r = (uint32_t)(wm * 32 + mt * 16 + lrow16);
            uint32_t addr = sa + swz(r * 128u + (uint32_t)lksel * 16u);
            ldm_x4(aF0[mt][0], aF0[mt][1], aF0[mt][2], aF0[mt][3], addr);
        }

        if (kt + 2 < NK) fill_stage(kt + 2, row0, n0, tid, sbase);
        CP_COMMIT();                    // uniform group accounting

        #pragma unroll
        for (int ks = 0; ks < 4; ks++) {
            const uint32_t kb = (uint32_t)ks * 32u;   // 32-byte k-slices
            const int cur = ks & 1;

            uint32_t aF[2][4];
            if (ks == 0) {
                #pragma unroll
                for (int mt = 0; mt < 2; mt++)
                    #pragma unroll
                    for (int q = 0; q < 4; q++) aF[mt][q] = aF0[mt][q];
            } else {
                #pragma unroll
                for (int mt = 0; mt < 2; mt++) {
                    uint32_t r = (uint32_t)(wm * 32 + mt * 16 + lrow16);
                    uint32_t addr = sa + swz(r * 128u + kb + (uint32_t)lksel * 16u);
                    ldm_x4(aF[mt][0], aF[mt][1], aF[mt][2], aF[mt][3], addr);
                }
            }
            if (ks < 3) {
                const uint32_t kbn = kb + 32u;
                #pragma unroll
                for (int np = 0; np < 4; np++) {
                    uint32_t n = (uint32_t)(wn * 64 + (np * 2 + (bgrp >> 1)) * 8 + brow);
                    uint32_t addr = sb + swz(n * 128u + kbn + (uint32_t)(bgrp & 1) * 16u);
                    uint32_t r0, r1, r2, r3;
                    ldm_x4(r0, r1, r2, r3, addr);
                    bF[cur ^ 1][np * 2][0] = r0; bF[cur ^ 1][np * 2][1] = r1;
                    bF[cur ^ 1][np * 2 + 1][0] = r2; bF[cur ^ 1][np * 2 + 1][1] = r3;
                }
            }
            #pragma unroll
            for (int mt = 0; mt < 2; mt++)
                #pragma unroll
                for (int nt = 0; nt < 8; nt++)
                    mma_s8(acc[mt][nt][0], acc[mt][nt][1],
                           acc[mt][nt][2], acc[mt][nt][3],
                           aF[mt][0], aF[mt][1], aF[mt][2], aF[mt][3],
                           bF[cur][nt][0], bF[cur][nt][1]);
        }
    }

    // epilogue: d = cnorm - SCALE2*dot - DOFF; fp16 store + per-chunk min
    const int lr = lane >> 2;           // 0..7
    const int lc = (lane & 3) * 2;
    #pragma unroll
    for (int mt = 0; mt < 2; mt++) {
        #pragma unroll
        for (int half = 0; half < 2; half++) {   // regs{0,1}: row lr; {2,3}: lr+8
            const int row = wm * 32 + mt * 16 + lr + half * 8;
            __half* drow = g_D + (size_t)(row0 + row) * KC + n0;
            float mn = 3.4e38f;
            #pragma unroll
            for (int nt = 0; nt < 8; nt++) {
                const int col = wn * 64 + nt * 8 + lc;
                float dx = fmaf(-SCALE2, (float)acc[mt][nt][half * 2 + 0],
                                s_cnorm[col])     - DOFF;
                float dy = fmaf(-SCALE2, (float)acc[mt][nt][half * 2 + 1],
                                s_cnorm[col + 1]) - DOFF;
                *reinterpret_cast<__half2*>(drow + col) = __floats2half2_rn(dx, dy);
                mn = fminf(mn, fminf(dx, dy));
            }
            mn = fminf(mn, __shfl_xor_sync(0xffffffffu, mn, 1));
            mn = fminf(mn, __shfl_xor_sync(0xffffffffu, mn, 2));
            if ((lane & 3) == 0)
                g_pmin[(size_t)(row0 + row) * NCHK + blockIdx.x * 2 + wn] = mn;
        }
    }
}

// ---------------- refine: pmin triage -> hot-chunk scan -> exact recheck -----
__global__ void __launch_bounds__(256)
refine_kernel(const float* __restrict__ x, const float* __restrict__ cen,
              float* __restrict__ out) {
    const int lane = threadIdx.x & 31;
    const int w    = threadIdx.x >> 5;
    const int row  = blockIdx.x * 8 + w;

    __shared__ int s_cand[8][CAP];
    __shared__ int s_cnt[8];
    if (lane == 0) s_cnt[w] = 0;
    __syncwarp();

    // 1) per-chunk mins
    const float pm = g_pmin[(size_t)row * NCHK + lane];
    float gmin = pm;
    #pragma unroll
    for (int o = 16; o > 0; o >>= 1)
        gmin = fminf(gmin, __shfl_xor_sync(0xffffffffu, gmin, o));
    const float th = gmin + MARGIN;
    unsigned chunkmask = __ballot_sync(0xffffffffu, pm <= th);

    // 2) scan only hot 64-col chunks
    while (chunkmask) {
        const int j = __ffs(chunkmask) - 1;
        chunkmask &= chunkmask - 1;
        const __half2 hv = reinterpret_cast<const __half2*>(
            g_D + (size_t)row * KC + j * 64)[lane];
        const float2 f = __half22float2(hv);
        if (f.x <= th) {
            int s = atomicAdd(&s_cnt[w], 1);
            if (s < CAP) s_cand[w][s] = j * 64 + lane * 2;
        }
        if (f.y <= th) {
            int s = atomicAdd(&s_cnt[w], 1);
            if (s < CAP) s_cand[w][s] = j * 64 + lane * 2 + 1;
        }
    }
    __syncwarp();
    const int cnt = min(s_cnt[w], CAP);

    if (cnt == 1) {
        if (lane == 0) out[row] = (float)s_cand[w][0];
        return;
    }

    // 3) exact fp32 recheck (warp-cooperative dot per candidate)
    const float4* xr = reinterpret_cast<const float4*>(x + (size_t)row * E);
    float4 xa[8];
    #pragma unroll
    for (int j = 0; j < 8; j++) xa[j] = xr[lane + 32 * j];

    float best_d = 3.4e38f;
    int   best_i = 0x7fffffff;
    for (int i = 0; i < cnt; i++) {
        const int c = s_cand[w][i];
        const float4* cr = reinterpret_cast<const float4*>(cen + (size_t)c * E);
        float p = 0.f;
        #pragma unroll
        for (int j = 0; j < 8; j++) {
            float4 b = cr[lane + 32 * j];
            p = fmaf(xa[j].x, b.x, p); p = fmaf(xa[j].y, b.y, p);
            p = fmaf(xa[j].z, b.z, p); p = fmaf(xa[j].w, b.w, p);
        }
        #pragma unroll
        for (int o = 16; o > 0; o >>= 1)
            p += __shfl_xor_sync(0xffffffffu, p, o);
        const float dd = fmaf(-2.f, p, g_cnorm[c]);
        if (dd < best_d || (dd == best_d && c < best_i)) { best_d = dd; best_i = c; }
    }
    if (lane == 0) out[row] = (float)best_i;
}

// ---------------- launch ------------------------------------------------------
extern "C" void kernel_launch(void* const* d_in, const int* in_sizes, int n_in,
                              void* d_out, int out_size) {
    const float* a0 = (const float*)d_in[0];
    const float* a1 = (const float*)d_in[1];
    const float* x;
    const float* cen;
    if (in_sizes[0] >= in_sizes[1]) { x = a0; cen = a1; }
    else                            { x = a1; cen = a0; }

    float* out = (float*)d_out;
    const int nrows = out_size;                  // 32000

    const int nxb = nrows * E / XBLK;            // 16000
    prologue_kernel<<<nxb + KC, 256>>>(x, cen, nxb);

    cudaFuncSetAttribute(gemm_s8_kernel,
                         cudaFuncAttributeMaxDynamicSharedMemorySize, GSMEM_TOTAL);
    dim3 ggrid(KC / BN, nrows / BM);             // (16, 250)
    gemm_s8_kernel<<<ggrid, GTHREADS, GSMEM_TOTAL>>>();

    refine_kernel<<<nrows / 8, 256>>>(x, cen, out);
}

// round 15
// speedup vs baseline: 2.0112x; 2.0112x over previous
#include <cuda_runtime.h>
#include <cuda_bf16.h>
#include <cuda_fp16.h>
#include <cstdint>
#include <cstddef>

#define DINLINE __device__ __forceinline__

namespace {
constexpr int E       = 1024;
constexpr int KC      = 2048;
constexpr int MAXROWS = 32000;

constexpr int BM = 128;          // CTA rows
constexpr int BN = 128;          // CTA centroids
constexpr int BK = 64;           // k-chunk (64 bf16 = 128B row, SW128-friendly)
constexpr int NK = E / BK;       // 16
constexpr int NSTAGE = 3;
constexpr int GTHREADS = 256;    // 8 warps: 4(m) x 2(n), warp tile 32x64

constexpr int STAGE_BYTES = (BM + BN) * BK * 2;     // 32KB
constexpr int OFF_B       = BM * BK * 2;            // B tile after A within stage
constexpr int OFF_CNORM   = NSTAGE * STAGE_BYTES;   // 96KB
constexpr int GSMEM_TOTAL = OFF_CNORM + BN * 4;     // 98816 -> 2 CTAs/SM

constexpr float DOFF   = 1024.0f;  // subtract before fp16 store
constexpr float MARGIN = 2.0f;     // >= 2*eps_bf16gemm (~1.2) + fp16 quant (0.25)
constexpr int   CAP    = 128;      // candidate cap per row
constexpr int   NCHK   = 32;       // 64-col min-chunks per row (2048/64)

constexpr int XBLK = 2048;         // x elements converted per prologue block
}

// ---------------- device scratch --------------------------------------------
__device__ __nv_bfloat16 g_x_bf[MAXROWS * E];   // 64MB
__device__ __nv_bfloat16 g_c_bf[KC * E];        // 4MB
__device__ __align__(16) __half g_D[(size_t)MAXROWS * KC]; // 131MB dists - DOFF
__device__ float  g_pmin[(size_t)MAXROWS * NCHK];          // 4MB per-chunk fp32 mins
__device__ float  g_cnorm[KC];

// ---------------- helpers ----------------------------------------------------
DINLINE uint32_t smem_u32(const void* p) {
    uint32_t a;
    asm("{ .reg .u64 t; cvta.to.shared.u64 t, %1; cvt.u32.u64 %0, t; }"
        : "=r"(a) : "l"(p));
    return a;
}
DINLINE uint32_t sw128(uint32_t o) { return o ^ ((o >> 3) & 0x70); }

DINLINE void cp16(uint32_t dst, const void* src) {
    asm volatile("cp.async.cg.shared.global [%0], [%1], 16;"
                 :: "r"(dst), "l"(src) : "memory");
}
#define CP_COMMIT()      asm volatile("cp.async.commit_group;" ::: "memory")
#define CP_WAIT_GROUP(n) asm volatile("cp.async.wait_group %0;" :: "n"(n) : "memory")

DINLINE void ldm_x4(uint32_t& r0, uint32_t& r1, uint32_t& r2, uint32_t& r3,
                    uint32_t addr) {
    asm volatile("ldmatrix.sync.aligned.m8n8.x4.shared.b16 {%0,%1,%2,%3}, [%4];"
                 : "=r"(r0), "=r"(r1), "=r"(r2), "=r"(r3) : "r"(addr));
}
DINLINE void mma_bf16(float& d0, float& d1, float& d2, float& d3,
                      uint32_t a0, uint32_t a1, uint32_t a2, uint32_t a3,
                      uint32_t b0, uint32_t b1) {
    asm volatile("mma.sync.aligned.m16n8k16.row.col.f32.bf16.bf16.f32 "
                 "{%0,%1,%2,%3}, {%4,%5,%6,%7}, {%8,%9}, {%0,%1,%2,%3};"
                 : "+f"(d0), "+f"(d1), "+f"(d2), "+f"(d3)
                 : "r"(a0), "r"(a1), "r"(a2), "r"(a3), "r"(b0), "r"(b1));
}

// ---------------- merged prologue: convert x + convert c + cnorm -------------
__global__ void prologue_kernel(const float* __restrict__ x,
                                const float* __restrict__ cen, int nxb) {
    const int tid = threadIdx.x;
    if (blockIdx.x < nxb) {
        const size_t base = (size_t)blockIdx.x * XBLK + (size_t)tid * 8;
        const float4* s4 = reinterpret_cast<const float4*>(x + base);
        float4 a = s4[0], b = s4[1];
        float v[8] = {a.x, a.y, a.z, a.w, b.x, b.y, b.z, b.w};
        uint4 o;
        unsigned short* p = reinterpret_cast<unsigned short*>(&o);
        #pragma unroll
        for (int j = 0; j < 8; j++)
            p[j] = __bfloat16_as_ushort(__float2bfloat16(v[j]));
        *reinterpret_cast<uint4*>(g_x_bf + base) = o;
    } else {
        const int row = blockIdx.x - nxb;
        const float4 a = reinterpret_cast<const float4*>(cen + (size_t)row * E)[tid];
        float v[4] = {a.x, a.y, a.z, a.w};
        uint2 o;
        unsigned short* p = reinterpret_cast<unsigned short*>(&o);
        float s = 0.f;
        #pragma unroll
        for (int j = 0; j < 4; j++) {
            p[j] = __bfloat16_as_ushort(__float2bfloat16(v[j]));
            s = fmaf(v[j], v[j], s);
        }
        *reinterpret_cast<uint2*>(g_c_bf + (size_t)row * E + tid * 4) = o;

        __shared__ float sm[8];
        #pragma unroll
        for (int off = 16; off > 0; off >>= 1)
            s += __shfl_down_sync(0xffffffffu, s, off);
        if ((tid & 31) == 0) sm[tid >> 5] = s;
        __syncthreads();
        if (tid < 8) {
            s = sm[tid];
            #pragma unroll
            for (int off = 4; off > 0; off >>= 1)
                s += __shfl_down_sync(0xffu, s, off);
            if (tid == 0) g_cnorm[row] = s;
        }
    }
}

// ---------------- GEMM (bf16, f32 acc): D = cnorm - 2*x.c - DOFF -------------
DINLINE void fill_stage(int kt, int row0, int n0, int tid, uint32_t sbase) {
    const uint32_t soff = (uint32_t)(kt % NSTAGE) * STAGE_BYTES;
    const int r    = tid >> 1;          // 0..127 (row within tile)
    const int half = tid & 1;           // k bytes 0-63 or 64-127
    const int k0   = kt * BK + half * 32;   // element offset
    const __nv_bfloat16* xs = g_x_bf + (size_t)(row0 + r) * E + k0;
    const __nv_bfloat16* cs = g_c_bf + (size_t)(n0 + r) * E + k0;
    const uint32_t base = (uint32_t)r * 128u + (uint32_t)half * 64u;
    #pragma unroll
    for (int q = 0; q < 4; q++)
        cp16(sbase + soff + sw128(base + q * 16), xs + q * 8);
    #pragma unroll
    for (int q = 0; q < 4; q++)
        cp16(sbase + soff + OFF_B + sw128(base + q * 16), cs + q * 8);
}

__global__ void __launch_bounds__(GTHREADS, 2)
gemm_bf16_kernel() {
    extern __shared__ __align__(1024) char smem[];
    const uint32_t sbase = smem_u32(smem);
    const int tid  = threadIdx.x;
    const int lane = tid & 31;
    const int wid  = tid >> 5;
    const int wm   = wid & 3;           // warp m: 0..3 (32 rows each)
    const int wn   = wid >> 2;          // warp n: 0..1 (64 cols each)
    const int n0   = blockIdx.x * BN;
    const int row0 = blockIdx.y * BM;

    float* s_cnorm = reinterpret_cast<float*>(smem + OFF_CNORM);
    if (tid < BN) s_cnorm[tid] = g_cnorm[n0 + tid];

    float acc[2][8][4];
    #pragma unroll
    for (int mt = 0; mt < 2; mt++)
        #pragma unroll
        for (int nt = 0; nt < 8; nt++)
            #pragma unroll
            for (int v = 0; v < 4; v++) acc[mt][nt][v] = 0.f;

    fill_stage(0, row0, n0, tid, sbase); CP_COMMIT();
    fill_stage(1, row0, n0, tid, sbase); CP_COMMIT();

    const int lrow16 = lane & 15;       // row within 16
    const int lksel  = lane >> 4;       // 0: k 0-7, 1: k 8-15 (x16B)
    const int bgrp   = lane >> 3;       // B x4 group 0..3
    const int brow   = lane & 7;

    for (int kt = 0; kt < NK; kt++) {
        CP_WAIT_GROUP(1);          // stage kt resident
        __syncthreads();           // visibility + all reads of slot (kt-1) done

        const uint32_t sa = sbase + (uint32_t)(kt % NSTAGE) * STAGE_BYTES;
        const uint32_t sb = sa + OFF_B;

        // preload slice-0 fragments first (before cp.async fill issues)
        uint32_t bF[2][8][2];
        #pragma unroll
        for (int np = 0; np < 4; np++) {
            uint32_t n = (uint32_t)(wn * 64 + (np * 2 + (bgrp >> 1)) * 8 + brow);
            uint32_t addr = sb + sw128(n * 128u + (uint32_t)(bgrp & 1) * 16u);
            uint32_t r0, r1, r2, r3;
            ldm_x4(r0, r1, r2, r3, addr);
            bF[0][np * 2][0] = r0; bF[0][np * 2][1] = r1;
            bF[0][np * 2 + 1][0] = r2; bF[0][np * 2 + 1][1] = r3;
        }
        uint32_t aF0[2][4];
        #pragma unroll
        for (int mt = 0; mt < 2; mt++) {
            uint32_t r = (uint32_t)(wm * 32 + mt * 16 + lrow16);
            uint32_t addr = sa + sw128(r * 128u + (uint32_t)lksel * 16u);
            ldm_x4(aF0[mt][0], aF0[mt][1], aF0[mt][2], aF0[mt][3], addr);
        }

        if (kt + 2 < NK) fill_stage(kt + 2, row0, n0, tid, sbase);
        CP_COMMIT();               // unconditional: uniform group accounting

        #pragma unroll
        for (int ks = 0; ks < 4; ks++) {
            const uint32_t kb = (uint32_t)ks * 32u;
            const int cur = ks & 1;

            uint32_t aF[2][4];
            if (ks == 0) {
                #pragma unroll
                for (int mt = 0; mt < 2; mt++)
                    #pragma unroll
                    for (int q = 0; q < 4; q++) aF[mt][q] = aF0[mt][q];
            } else {
                #pragma unroll
                for (int mt = 0; mt < 2; mt++) {
                    uint32_t r = (uint32_t)(wm * 32 + mt * 16 + lrow16);
                    uint32_t addr = sa + sw128(r * 128u + kb + (uint32_t)lksel * 16u);
                    ldm_x4(aF[mt][0], aF[mt][1], aF[mt][2], aF[mt][3], addr);
                }
            }
            if (ks < 3) {
                const uint32_t kbn = kb + 32u;
                #pragma unroll
                for (int np = 0; np < 4; np++) {
                    uint32_t n = (uint32_t)(wn * 64 + (np * 2 + (bgrp >> 1)) * 8 + brow);
                    uint32_t addr = sb + sw128(n * 128u + kbn + (uint32_t)(bgrp & 1) * 16u);
                    uint32_t r0, r1, r2, r3;
                    ldm_x4(r0, r1, r2, r3, addr);
                    bF[cur ^ 1][np * 2][0] = r0; bF[cur ^ 1][np * 2][1] = r1;
                    bF[cur ^ 1][np * 2 + 1][0] = r2; bF[cur ^ 1][np * 2 + 1][1] = r3;
                }
            }
            #pragma unroll
            for (int mt = 0; mt < 2; mt++)
                #pragma unroll
                for (int nt = 0; nt < 8; nt++)
                    mma_bf16(acc[mt][nt][0], acc[mt][nt][1],
                             acc[mt][nt][2], acc[mt][nt][3],
                             aF[mt][0], aF[mt][1], aF[mt][2], aF[mt][3],
                             bF[cur][nt][0], bF[cur][nt][1]);
        }
    }

    // epilogue: d-DOFF stored fp16 + fp32 per-row 64-col chunk min (pmin)
    const int lr = lane >> 2;           // 0..7
    const int lc = (lane & 3) * 2;
    #pragma unroll
    for (int mt = 0; mt < 2; mt++) {
        #pragma unroll
        for (int half = 0; half < 2; half++) {   // v{0,1} vs v{2,3}: row +0/+8
            const int row = wm * 32 + mt * 16 + lr + half * 8;
            __half* drow = g_D + (size_t)(row0 + row) * KC + n0;
            float mn = 3.4e38f;
            #pragma unroll
            for (int nt = 0; nt < 8; nt++) {
                const int col = wn * 64 + nt * 8 + lc;
                float dx = fmaf(-2.f, acc[mt][nt][half * 2 + 0], s_cnorm[col])     - DOFF;
                float dy = fmaf(-2.f, acc[mt][nt][half * 2 + 1], s_cnorm[col + 1]) - DOFF;
                *reinterpret_cast<__half2*>(drow + col) = __floats2half2_rn(dx, dy);
                mn = fminf(mn, fminf(dx, dy));
            }
            // min across the 4 lanes covering this row's 64 cols
            mn = fminf(mn, __shfl_xor_sync(0xffffffffu, mn, 1));
            mn = fminf(mn, __shfl_xor_sync(0xffffffffu, mn, 2));
            if ((lane & 3) == 0)
                g_pmin[(size_t)(row0 + row) * NCHK + blockIdx.x * 2 + wn] = mn;
        }
    }
}

// ---------------- refine: pmin triage -> hot-chunk scan -> exact recheck -----
__global__ void __launch_bounds__(256)
refine_kernel(const float* __restrict__ x, const float* __restrict__ cen,
              float* __restrict__ out) {
    const int lane = threadIdx.x & 31;
    const int w    = threadIdx.x >> 5;
    const int row  = blockIdx.x * 8 + w;

    __shared__ int s_cand[8][CAP];
    __shared__ int s_cnt[8];
    if (lane == 0) s_cnt[w] = 0;
    __syncwarp();

    // 1) per-chunk fp32 mins: one per lane
    const float pm = g_pmin[(size_t)row * NCHK + lane];
    float gmin = pm;
    #pragma unroll
    for (int o = 16; o > 0; o >>= 1)
        gmin = fminf(gmin, __shfl_xor_sync(0xffffffffu, gmin, o));
    const float th = gmin + MARGIN;
    unsigned chunkmask = __ballot_sync(0xffffffffu, pm <= th);

    // 2) scan only hot 64-col chunks (usually exactly one)
    while (chunkmask) {
        const int j = __ffs(chunkmask) - 1;
        chunkmask &= chunkmask - 1;
        const __half2 hv = reinterpret_cast<const __half2*>(
            g_D + (size_t)row * KC + j * 64)[lane];
        const float2 f = __half22float2(hv);
        if (f.x <= th) {
            int s = atomicAdd(&s_cnt[w], 1);
            if (s < CAP) s_cand[w][s] = j * 64 + lane * 2;
        }
        if (f.y <= th) {
            int s = atomicAdd(&s_cnt[w], 1);
            if (s < CAP) s_cand[w][s] = j * 64 + lane * 2 + 1;
        }
    }
    __syncwarp();
    const int cnt = min(s_cnt[w], CAP);

    if (cnt == 1) {                 // single candidate: it is the argmin
        if (lane == 0) out[row] = (float)s_cand[w][0];
        return;
    }

    // 3) exact fp32 recheck (warp-cooperative dot per candidate)
    const float4* xr = reinterpret_cast<const float4*>(x + (size_t)row * E);
    float4 xa[8];
    #pragma unroll
    for (int j = 0; j < 8; j++) xa[j] = xr[lane + 32 * j];

    float best_d = 3.4e38f;
    int   best_i = 0x7fffffff;
    for (int i = 0; i < cnt; i++) {
        const int c = s_cand[w][i];
        const float4* cr = reinterpret_cast<const float4*>(cen + (size_t)c * E);
        float p = 0.f;
        #pragma unroll
        for (int j = 0; j < 8; j++) {
            float4 b = cr[lane + 32 * j];
            p = fmaf(xa[j].x, b.x, p); p = fmaf(xa[j].y, b.y, p);
            p = fmaf(xa[j].z, b.z, p); p = fmaf(xa[j].w, b.w, p);
        }
        #pragma unroll
        for (int o = 16; o > 0; o >>= 1)
            p += __shfl_xor_sync(0xffffffffu, p, o);
        const float dd = fmaf(-2.f, p, g_cnorm[c]);
        if (dd < best_d || (dd == best_d && c < best_i)) { best_d = dd; best_i = c; }
    }
    if (lane == 0) out[row] = (float)best_i;
}

// ---------------- launch ------------------------------------------------------
extern "C" void kernel_launch(void* const* d_in, const int* in_sizes, int n_in,
                              void* d_out, int out_size) {
    const float* a0 = (const float*)d_in[0];
    const float* a1 = (const float*)d_in[1];
    const float* x;
    const float* cen;
    if (in_sizes[0] >= in_sizes[1]) { x = a0; cen = a1; }
    else                            { x = a1; cen = a0; }

    float* out = (float*)d_out;
    const int nrows = out_size;                  // 32000

    const int nxb = nrows * E / XBLK;            // 16000
    prologue_kernel<<<nxb + KC, 256>>>(x, cen, nxb);

    cudaFuncSetAttribute(gemm_bf16_kernel,
                         cudaFuncAttributeMaxDynamicSharedMemorySize, GSMEM_TOTAL);
    dim3 ggrid(KC / BN, nrows / BM);             // (16, 250)
    gemm_bf16_kernel<<<ggrid, GTHREADS, GSMEM_TOTAL>>>();

    refine_kernel<<<nrows / 8, 256>>>(x, cen, out);
}